// round 13
// baseline (speedup 1.0000x reference)
#include <cuda_runtime.h>
#include <cuda.h>
#include <cuda_fp16.h>
#include <cstdint>

// Problem constants
#define M_DIM 8192
#define K_DIM 4096
#define N_DIM 11008
#define NP    (N_DIM / 8)

// tcgen05 GEMM: CTA tile 256x256, BK=64, 3 stages, TMA, 8-CTA cluster along M
// with B-tile multicast cooperative slicing (dedup-window win needs csz>4).
#define BM 256
#define BN 256
#define BK 64
#define CLUSTER 8
#define STAGE_A_BYTES (BM * BK * 2)                     // 32768
#define STAGE_B_BYTES (BN * BK * 2)                     // 32768
#define STAGE_BYTES   (STAGE_A_BYTES + STAGE_B_BYTES)   // 65536
#define SMEM_STAGES   (3 * STAGE_BYTES)                 // 196608
#define SMEM_TOTAL    (SMEM_STAGES + 1024 + 128)
#define B_SLICE_ROWS  (BN / CLUSTER)                    // 32
#define B_SLICE_BYTES (B_SLICE_ROWS * BK * 2)           // 4096

// Static device scratch
__device__ __half g_Wt[(size_t)N_DIM * K_DIM];  // W transposed [N][K], fp16
__device__ __half g_X [(size_t)M_DIM * K_DIM];  // activations fp16

// ---------------------------------------------------------------------------
// Prep: convert x fp32->fp16 AND dequant AWQ int4 -> g_Wt[n][k], one kernel.
// Blocks [0, n_conv) do convert; the rest do the dequant-transpose tiles.
// ---------------------------------------------------------------------------
#define N_CONV_BLOCKS (M_DIM * K_DIM / 4 / 256)         // 32768
#define N_DQ_BLOCKS   ((K_DIM / 64) * (N_DIM / 256))    // 2752

__global__ __launch_bounds__(256)
void prep_kernel(const float* __restrict__ x,
                 const int* __restrict__ qweight,
                 const int* __restrict__ qzeros,
                 const float* __restrict__ scales) {
    const int tid = threadIdx.x;
    if (blockIdx.x < N_CONV_BLOCKS) {
        int i = (blockIdx.x * 256 + tid) * 4;
        float4 v = *reinterpret_cast<const float4*>(x + i);
        __half h[4];
        h[0] = __float2half(v.x); h[1] = __float2half(v.y);
        h[2] = __float2half(v.z); h[3] = __float2half(v.w);
        *reinterpret_cast<uint2*>(&g_X[i]) = *reinterpret_cast<uint2*>(h);
        return;
    }
    const int bid = blockIdx.x - N_CONV_BLOCKS;
    __shared__ __half s[256][64];
    const int k0 = (bid & 63) * 64;          // 64 k-tiles
    const int n0 = (bid >> 6) * 256;         // 43 n-tiles
    const int g  = k0 >> 7;
    const int c0 = n0 >> 3;

#pragma unroll
    for (int i = 0; i < 8; i++) {
        int lin = tid + 256 * i;
        int cl  = lin & 31;
        int kl  = lin >> 5;
        uint32_t w = (uint32_t)qweight[(size_t)(k0 + kl) * NP + c0 + cl];
        uint32_t z = (uint32_t)qzeros[(size_t)g * NP + c0 + cl];
        const float* sp = scales + (size_t)g * N_DIM + n0 + cl * 8;
#pragma unroll
        for (int j = 0; j < 8; j++) {
            float wi = (float)((w >> (4 * j)) & 15u);
            float zi = (float)((z >> (4 * j)) & 15u);
            __half v = __float2half((wi - zi) * sp[j]);
            int nl = cl * 8 + j;
            int phys16 = (kl >> 3) ^ ((nl >> 3) & 7);
            s[nl][(phys16 << 3) | (kl & 7)] = v;
        }
    }
    __syncthreads();
#pragma unroll
    for (int i = 0; i < 8; i++) {
        int idx = tid + 256 * i;
        int r = idx >> 3, q = idx & 7;
        int phys16 = q ^ ((r >> 3) & 7);
        uint4 v = *reinterpret_cast<uint4*>(&s[r][phys16 << 3]);
        *reinterpret_cast<uint4*>(&g_Wt[(size_t)(n0 + r) * K_DIM + k0 + q * 8]) = v;
    }
}

// ---------------------------------------------------------------------------
// tcgen05 / TMA helpers (device pass targets sm_103a family)
// ---------------------------------------------------------------------------
#if defined(__CUDA_ARCH__) && (defined(__CUDA_ARCH_FEAT_SM103_ALL) || defined(__CUDA_ARCH_FEAT_SM100_ALL) || defined(__CUDA_ARCH_FEAT_SM101_ALL))
#define TC_LIVE 1
#endif

#ifdef TC_LIVE
__device__ __forceinline__ uint32_t elect_one() {
    uint32_t p;
    asm volatile("{\n\t.reg .pred P;\n\telect.sync _|P, 0xFFFFFFFF;\n\t"
                 "selp.b32 %0, 1, 0, P;\n\t}" : "=r"(p));
    return p;
}
__device__ __forceinline__ uint32_t cluster_rank() {
    uint32_t r;
    asm("mov.u32 %0, %%cluster_ctarank;" : "=r"(r));
    return r;
}
__device__ __forceinline__ void mbar_init(uint32_t a, uint32_t cnt) {
    asm volatile("mbarrier.init.shared.b64 [%0], %1;" :: "r"(a), "r"(cnt) : "memory");
}
__device__ __forceinline__ void mbar_wait(uint32_t a, uint32_t parity) {
    asm volatile("{\n\t.reg .pred P;\n\tLW%=:\n\t"
                 "mbarrier.try_wait.parity.acquire.cta.shared::cta.b64 P, [%0], %1;\n\t"
                 "@!P bra LW%=;\n\t}" :: "r"(a), "r"(parity) : "memory");
}
__device__ __forceinline__ void mbar_expect_tx(uint32_t a, uint32_t bytes) {
    asm volatile("mbarrier.arrive.expect_tx.shared.b64 _, [%0], %1;"
                 :: "r"(a), "r"(bytes) : "memory");
}
__device__ __forceinline__ void tma_2d(uint32_t dst, const void* map,
                                       int32_t x, int32_t y, uint32_t mbar) {
    asm volatile("cp.async.bulk.tensor.2d.shared::cta.global.tile"
                 ".mbarrier::complete_tx::bytes [%0], [%1, {%2, %3}], [%4];"
                 :: "r"(dst), "l"(map), "r"(x), "r"(y), "r"(mbar) : "memory");
}
__device__ __forceinline__ void tma_2d_mc(uint32_t dst, const void* map,
                                          int32_t x, int32_t y, uint32_t mbar,
                                          uint16_t mask) {
    asm volatile("cp.async.bulk.tensor.2d.shared::cluster.global.tile"
                 ".mbarrier::complete_tx::bytes.multicast::cluster "
                 "[%0], [%1, {%2, %3}], [%4], %5;"
                 :: "r"(dst), "l"(map), "r"(x), "r"(y), "r"(mbar), "h"(mask)
                 : "memory");
}
__device__ __forceinline__ void tc_commit(uint32_t mbar) {
    asm volatile("tcgen05.commit.cta_group::1.mbarrier::arrive::one.shared::cluster.b64 [%0];"
                 :: "r"(mbar) : "memory");
}
__device__ __forceinline__ void tc_commit_mc(uint32_t mbar, uint16_t mask) {
    asm volatile("tcgen05.commit.cta_group::1.mbarrier::arrive::one"
                 ".shared::cluster.multicast::cluster.b64 [%0], %1;"
                 :: "r"(mbar), "h"(mask) : "memory");
}
__device__ __forceinline__ void mma_f16_ss(uint32_t d, uint64_t ad, uint64_t bd,
                                           uint32_t idesc, uint32_t en) {
    asm volatile("{\n\t.reg .pred p;\n\tsetp.ne.u32 p, %4, 0;\n\t"
                 "tcgen05.mma.cta_group::1.kind::f16 [%0], %1, %2, %3, {%5,%5,%5,%5}, p;\n\t}"
                 :: "r"(d), "l"(ad), "l"(bd), "r"(idesc), "r"(en), "r"(0u) : "memory");
}
// K-major SW128 descriptor: layout=2, version=1, SBO=64, LBO=1 (proven)
__device__ __forceinline__ uint64_t make_desc(uint32_t smem_addr) {
    return ((uint64_t)2 << 61) | ((uint64_t)1 << 46) | ((uint64_t)64 << 32) |
           ((uint64_t)1 << 16) | (((uint64_t)(smem_addr >> 4)) & 0x3FFF);
}
__device__ __forceinline__ void ldtm_x32(uint32_t* r, uint32_t tmem) {
    asm volatile(
        "tcgen05.ld.sync.aligned.32x32b.x32.b32 "
        "{%0,%1,%2,%3,%4,%5,%6,%7,%8,%9,%10,%11,%12,%13,%14,%15,"
        "%16,%17,%18,%19,%20,%21,%22,%23,%24,%25,%26,%27,%28,%29,%30,%31}, [%32];"
        : "=r"(r[0]),"=r"(r[1]),"=r"(r[2]),"=r"(r[3]),"=r"(r[4]),"=r"(r[5]),"=r"(r[6]),"=r"(r[7]),
          "=r"(r[8]),"=r"(r[9]),"=r"(r[10]),"=r"(r[11]),"=r"(r[12]),"=r"(r[13]),"=r"(r[14]),"=r"(r[15]),
          "=r"(r[16]),"=r"(r[17]),"=r"(r[18]),"=r"(r[19]),"=r"(r[20]),"=r"(r[21]),"=r"(r[22]),"=r"(r[23]),
          "=r"(r[24]),"=r"(r[25]),"=r"(r[26]),"=r"(r[27]),"=r"(r[28]),"=r"(r[29]),"=r"(r[30]),"=r"(r[31])
        : "r"(tmem));
}
#endif  // TC_LIVE

// 288 threads. Warp 0 elect = TMA producer; warp 8 elect = MMA issuer;
// warps 0-7 = epilogue. Cluster (8,1,1) along bm: the 8 CTAs share one B tile
// (same bn); each loads a 32-row slice and multicasts it to all 8.
__global__ __launch_bounds__(288, 1) __cluster_dims__(CLUSTER, 1, 1)
void gemm_tc_kernel(const __grid_constant__ CUtensorMap tma_a,
                    const __grid_constant__ CUtensorMap tma_b,
                    float* __restrict__ Out) {
#ifdef TC_LIVE
    extern __shared__ char smem_raw[];
    char* smem = (char*)(((uintptr_t)smem_raw + 1023) & ~(uintptr_t)1023);
    const uint32_t sbase = (uint32_t)__cvta_generic_to_shared(smem);
    const uint32_t mbarb = sbase + SMEM_STAGES;
    // full[s]: +0,+8,+16 ; empty[s]: +24,+32,+40 ; fin: +48 ; tmem ptr: +56

    const int tid  = threadIdx.x;
    const int wid  = tid >> 5;
    const int lane = tid & 31;
    const uint32_t rank = cluster_rank();
    const int bm = blockIdx.x * BM;
    const int bn = blockIdx.y * BN;
    const uint16_t ALLMASK = (uint16_t)((1u << CLUSTER) - 1u);  // 0xFF

    if (tid == 0) {
#pragma unroll
        for (int s = 0; s < 3; s++) {
            mbar_init(mbarb +      8 * s, 1);        // full: 1 expect_tx arrival
            mbar_init(mbarb + 24 + 8 * s, CLUSTER);  // empty: 8 commits (cluster)
        }
        mbar_init(mbarb + 48, 1);                    // fin
    }
    if (wid == 8) {
        asm volatile("tcgen05.alloc.cta_group::1.sync.aligned.shared::cta.b32 [%0], %1;"
                     :: "r"(mbarb + 56), "r"(512) : "memory");
        asm volatile("tcgen05.relinquish_alloc_permit.cta_group::1.sync.aligned;");
    }
    __syncthreads();
    // All cluster CTAs' barriers must exist before any multicast TMA / commit.
    asm volatile("barrier.cluster.arrive.aligned;" ::: "memory");
    asm volatile("barrier.cluster.wait.aligned;" ::: "memory");

    uint32_t tmem;
    asm volatile("ld.shared.b32 %0, [%1];" : "=r"(tmem) : "r"(mbarb + 56));

    const int KT = K_DIM / BK;  // 64

    if (wid == 0 && elect_one()) {
        // ---------------- TMA producer (1 thread) ----------------
        for (int kt = 0; kt < KT; kt++) {
            const int s = kt % 3;
            const uint32_t e_par = ((kt / 3) & 1) ^ 1;   // first 3 uses pass
            mbar_wait(mbarb + 24 + 8 * s, e_par);

            const uint32_t full = mbarb + 8 * s;
            // A 32KB (own) + B 8 x 4KB multicast slices (one from each CTA)
            mbar_expect_tx(full, STAGE_BYTES);
            uint32_t a_s = sbase + s * STAGE_BYTES;
            uint32_t b_s = a_s + STAGE_A_BYTES;
            tma_2d(a_s, &tma_a, kt * BK, bm, full);
            tma_2d_mc(b_s + rank * B_SLICE_BYTES, &tma_b,
                      kt * BK, bn + (int)rank * B_SLICE_ROWS, full, ALLMASK);
        }
    } else if (wid == 8 && elect_one()) {
        // ---------------- MMA issuer (1 thread) ----------------
        const uint32_t idesc = (8u << 24) | (16u << 17) | (1u << 4);  // M=128,N=128,f16->f32
        for (int kt = 0; kt < KT; kt++) {
            const int s = kt % 3;
            mbar_wait(mbarb + 8 * s, (kt / 3) & 1);

            uint32_t a_s = sbase + s * STAGE_BYTES;
            uint32_t b_s = a_s + STAGE_A_BYTES;
            uint64_t ad0 = make_desc(a_s);
            uint64_t ad1 = make_desc(a_s + 16384);
            uint64_t bd0 = make_desc(b_s);
            uint64_t bd1 = make_desc(b_s + 16384);
#pragma unroll
            for (int ks = 0; ks < 4; ks++) {
                uint32_t en = (kt > 0 || ks > 0) ? 1u : 0u;
                mma_f16_ss(tmem,       ad0 + ks * 2, bd0 + ks * 2, idesc, en);
                mma_f16_ss(tmem + 128, ad0 + ks * 2, bd1 + ks * 2, idesc, en);
                mma_f16_ss(tmem + 256, ad1 + ks * 2, bd0 + ks * 2, idesc, en);
                mma_f16_ss(tmem + 384, ad1 + ks * 2, bd1 + ks * 2, idesc, en);
            }
            // Recycle stage in ALL cluster CTAs when this CTA's MMAs complete.
            tc_commit_mc(mbarb + 24 + 8 * s, ALLMASK);
        }
        tc_commit(mbarb + 48);
    }

    // All threads: wait for all MMAs to drain
    mbar_wait(mbarb + 48, 0);
    asm volatile("tcgen05.fence::after_thread_sync;" ::: "memory");

    // Epilogue (warps 0-7): warp w -> M-half (w>>2), rows (w&3)*32
    if (wid < 8) {
        const int h   = wid >> 2;
        const int row = bm + h * 128 + (wid & 3) * 32 + lane;
        float* dst = Out + (size_t)row * N_DIM + bn;
        const uint32_t tm = tmem + h * 256;
#pragma unroll
        for (int b = 0; b < 8; b++) {
            uint32_t v[32];
            ldtm_x32(v, tm + b * 32);
            asm volatile("tcgen05.wait::ld.sync.aligned;" ::: "memory");
#pragma unroll
            for (int i = 0; i < 8; i++) {
                float4 f;
                f.x = __uint_as_float(v[4 * i + 0]);
                f.y = __uint_as_float(v[4 * i + 1]);
                f.z = __uint_as_float(v[4 * i + 2]);
                f.w = __uint_as_float(v[4 * i + 3]);
                *reinterpret_cast<float4*>(dst + b * 32 + i * 4) = f;
            }
        }
    }
    __syncthreads();
    if (wid == 8) {
        asm volatile("tcgen05.dealloc.cta_group::1.sync.aligned.b32 %0, %1;"
                     :: "r"(tmem), "r"(512));
    }
    // No CTA may exit while peers could still multicast into its smem.
    asm volatile("barrier.cluster.arrive.aligned;" ::: "memory");
    asm volatile("barrier.cluster.wait.aligned;" ::: "memory");
#endif  // TC_LIVE
}

// ---------------------------------------------------------------------------
typedef CUresult (*EncodeTiledFn)(
    CUtensorMap*, CUtensorMapDataType, cuuint32_t, void*,
    const cuuint64_t*, const cuuint64_t*, const cuuint32_t*, const cuuint32_t*,
    CUtensorMapInterleave, CUtensorMapSwizzle, CUtensorMapL2promotion,
    CUtensorMapFloatOOBfill);

extern "C" void kernel_launch(void* const* d_in, const int* in_sizes, int n_in,
                              void* d_out, int out_size) {
    const float* x  = (const float*)d_in[0];   // [4,2048,4096] fp32 (upcast fp16)
    const int*   qw = (const int*)d_in[1];     // [4096,1376]
    const int*   qz = (const int*)d_in[2];     // [32,1376]
    const float* sc = (const float*)d_in[3];   // [32,11008] fp32 (upcast fp16)
    float* out = (float*)d_out;                // [4,2048,11008] fp32

    cudaFuncSetAttribute(gemm_tc_kernel, cudaFuncAttributeMaxDynamicSharedMemorySize,
                         SMEM_TOTAL);

    // Build TMA descriptors for g_X [M,K] and g_Wt [N,K] (SW128, fp16).
    void* pX = nullptr; void* pW = nullptr;
    cudaGetSymbolAddress(&pX, g_X);
    cudaGetSymbolAddress(&pW, g_Wt);
    EncodeTiledFn enc = nullptr;
    cudaDriverEntryPointQueryResult qr;
    cudaGetDriverEntryPointByVersion("cuTensorMapEncodeTiled", (void**)&enc,
                                     12000, cudaEnableDefault, &qr);
    CUtensorMap ta, tb;
    {
        cuuint64_t dims[2] = {K_DIM, M_DIM};
        cuuint64_t strides[1] = {K_DIM * 2};
        cuuint32_t box[2] = {BK, BM};            // 64 x 256 (box0 = 128B = SW128)
        cuuint32_t es[2] = {1, 1};
        enc(&ta, CU_TENSOR_MAP_DATA_TYPE_FLOAT16, 2, pX, dims, strides, box, es,
            CU_TENSOR_MAP_INTERLEAVE_NONE, CU_TENSOR_MAP_SWIZZLE_128B,
            CU_TENSOR_MAP_L2_PROMOTION_L2_128B, CU_TENSOR_MAP_FLOAT_OOB_FILL_NONE);
    }
    {
        cuuint64_t dims[2] = {K_DIM, N_DIM};
        cuuint64_t strides[1] = {K_DIM * 2};
        cuuint32_t box[2] = {BK, B_SLICE_ROWS};  // 64 x 32 (cooperative slice)
        cuuint32_t es[2] = {1, 1};
        enc(&tb, CU_TENSOR_MAP_DATA_TYPE_FLOAT16, 2, pW, dims, strides, box, es,
            CU_TENSOR_MAP_INTERLEAVE_NONE, CU_TENSOR_MAP_SWIZZLE_128B,
            CU_TENSOR_MAP_L2_PROMOTION_L2_128B, CU_TENSOR_MAP_FLOAT_OOB_FILL_NONE);
    }

    // Fused prep: x fp32->fp16 + weight dequant-transpose (DRAM-bound, overlapped)
    prep_kernel<<<N_CONV_BLOCKS + N_DQ_BLOCKS, 256>>>(x, qw, qz, sc);

    dim3 grid(M_DIM / BM, N_DIM / BN);           // (32, 43); clusters of 8 on x
    gemm_tc_kernel<<<grid, 288, SMEM_TOTAL>>>(ta, tb, out);
}

// round 14
// speedup vs baseline: 1.1714x; 1.1714x over previous
#include <cuda_runtime.h>
#include <cuda.h>
#include <cuda_fp16.h>
#include <cstdint>

// Problem constants
#define M_DIM 8192
#define K_DIM 4096
#define N_DIM 11008
#define NP    (N_DIM / 8)

// tcgen05 GEMM: CTA tile 256x256, BK=64, 3 stages, TMA, 4-CTA cluster along M.
// B multicast (cooperative slicing, MC=1 fetch at csz=4). A and B have
// SEPARATE barrier domains: A recycles locally, only B couples the cluster.
#define BM 256
#define BN 256
#define BK 64
#define CLUSTER 4
#define A_STAGE_BYTES (BM * BK * 2)                     // 32768
#define B_STAGE_BYTES (BN * BK * 2)                     // 32768
#define SMEM_A_BASE   0
#define SMEM_B_BASE   (3 * A_STAGE_BYTES)               // 98304
#define SMEM_STAGES   (6 * A_STAGE_BYTES)               // 196608
#define SMEM_TOTAL    (SMEM_STAGES + 1024 + 128)
#define B_SLICE_ROWS  (BN / CLUSTER)                    // 64
#define B_SLICE_BYTES (B_SLICE_ROWS * BK * 2)           // 8192

// Static device scratch
__device__ __half g_Wt[(size_t)N_DIM * K_DIM];  // W transposed [N][K], fp16
__device__ __half g_X [(size_t)M_DIM * K_DIM];  // activations fp16

// ---------------------------------------------------------------------------
// Prep: convert x fp32->fp16 AND dequant AWQ int4 -> g_Wt[n][k], one kernel.
// ---------------------------------------------------------------------------
#define N_CONV_BLOCKS (M_DIM * K_DIM / 4 / 256)         // 32768
#define N_DQ_BLOCKS   ((K_DIM / 64) * (N_DIM / 256))    // 2752

__global__ __launch_bounds__(256)
void prep_kernel(const float* __restrict__ x,
                 const int* __restrict__ qweight,
                 const int* __restrict__ qzeros,
                 const float* __restrict__ scales) {
    const int tid = threadIdx.x;
    if (blockIdx.x < N_CONV_BLOCKS) {
        int i = (blockIdx.x * 256 + tid) * 4;
        float4 v = *reinterpret_cast<const float4*>(x + i);
        __half h[4];
        h[0] = __float2half(v.x); h[1] = __float2half(v.y);
        h[2] = __float2half(v.z); h[3] = __float2half(v.w);
        *reinterpret_cast<uint2*>(&g_X[i]) = *reinterpret_cast<uint2*>(h);
        return;
    }
    const int bid = blockIdx.x - N_CONV_BLOCKS;
    __shared__ __half s[256][64];
    const int k0 = (bid & 63) * 64;
    const int n0 = (bid >> 6) * 256;
    const int g  = k0 >> 7;
    const int c0 = n0 >> 3;

#pragma unroll
    for (int i = 0; i < 8; i++) {
        int lin = tid + 256 * i;
        int cl  = lin & 31;
        int kl  = lin >> 5;
        uint32_t w = (uint32_t)qweight[(size_t)(k0 + kl) * NP + c0 + cl];
        uint32_t z = (uint32_t)qzeros[(size_t)g * NP + c0 + cl];
        const float* sp = scales + (size_t)g * N_DIM + n0 + cl * 8;
#pragma unroll
        for (int j = 0; j < 8; j++) {
            float wi = (float)((w >> (4 * j)) & 15u);
            float zi = (float)((z >> (4 * j)) & 15u);
            __half v = __float2half((wi - zi) * sp[j]);
            int nl = cl * 8 + j;
            int phys16 = (kl >> 3) ^ ((nl >> 3) & 7);
            s[nl][(phys16 << 3) | (kl & 7)] = v;
        }
    }
    __syncthreads();
#pragma unroll
    for (int i = 0; i < 8; i++) {
        int idx = tid + 256 * i;
        int r = idx >> 3, q = idx & 7;
        int phys16 = q ^ ((r >> 3) & 7);
        uint4 v = *reinterpret_cast<uint4*>(&s[r][phys16 << 3]);
        *reinterpret_cast<uint4*>(&g_Wt[(size_t)(n0 + r) * K_DIM + k0 + q * 8]) = v;
    }
}

// ---------------------------------------------------------------------------
// tcgen05 / TMA helpers (device pass targets sm_103a family)
// ---------------------------------------------------------------------------
#if defined(__CUDA_ARCH__) && (defined(__CUDA_ARCH_FEAT_SM103_ALL) || defined(__CUDA_ARCH_FEAT_SM100_ALL) || defined(__CUDA_ARCH_FEAT_SM101_ALL))
#define TC_LIVE 1
#endif

#ifdef TC_LIVE
__device__ __forceinline__ uint32_t elect_one() {
    uint32_t p;
    asm volatile("{\n\t.reg .pred P;\n\telect.sync _|P, 0xFFFFFFFF;\n\t"
                 "selp.b32 %0, 1, 0, P;\n\t}" : "=r"(p));
    return p;
}
__device__ __forceinline__ uint32_t cluster_rank() {
    uint32_t r;
    asm("mov.u32 %0, %%cluster_ctarank;" : "=r"(r));
    return r;
}
__device__ __forceinline__ void mbar_init(uint32_t a, uint32_t cnt) {
    asm volatile("mbarrier.init.shared.b64 [%0], %1;" :: "r"(a), "r"(cnt) : "memory");
}
__device__ __forceinline__ void mbar_wait(uint32_t a, uint32_t parity) {
    asm volatile("{\n\t.reg .pred P;\n\tLW%=:\n\t"
                 "mbarrier.try_wait.parity.acquire.cta.shared::cta.b64 P, [%0], %1;\n\t"
                 "@!P bra LW%=;\n\t}" :: "r"(a), "r"(parity) : "memory");
}
__device__ __forceinline__ void mbar_expect_tx(uint32_t a, uint32_t bytes) {
    asm volatile("mbarrier.arrive.expect_tx.shared.b64 _, [%0], %1;"
                 :: "r"(a), "r"(bytes) : "memory");
}
__device__ __forceinline__ void tma_2d(uint32_t dst, const void* map,
                                       int32_t x, int32_t y, uint32_t mbar) {
    asm volatile("cp.async.bulk.tensor.2d.shared::cta.global.tile"
                 ".mbarrier::complete_tx::bytes [%0], [%1, {%2, %3}], [%4];"
                 :: "r"(dst), "l"(map), "r"(x), "r"(y), "r"(mbar) : "memory");
}
__device__ __forceinline__ void tma_2d_mc(uint32_t dst, const void* map,
                                          int32_t x, int32_t y, uint32_t mbar,
                                          uint16_t mask) {
    asm volatile("cp.async.bulk.tensor.2d.shared::cluster.global.tile"
                 ".mbarrier::complete_tx::bytes.multicast::cluster "
                 "[%0], [%1, {%2, %3}], [%4], %5;"
                 :: "r"(dst), "l"(map), "r"(x), "r"(y), "r"(mbar), "h"(mask)
                 : "memory");
}
__device__ __forceinline__ void tc_commit(uint32_t mbar) {
    asm volatile("tcgen05.commit.cta_group::1.mbarrier::arrive::one.shared::cluster.b64 [%0];"
                 :: "r"(mbar) : "memory");
}
__device__ __forceinline__ void tc_commit_mc(uint32_t mbar, uint16_t mask) {
    asm volatile("tcgen05.commit.cta_group::1.mbarrier::arrive::one"
                 ".shared::cluster.multicast::cluster.b64 [%0], %1;"
                 :: "r"(mbar), "h"(mask) : "memory");
}
__device__ __forceinline__ void mma_f16_ss(uint32_t d, uint64_t ad, uint64_t bd,
                                           uint32_t idesc, uint32_t en) {
    asm volatile("{\n\t.reg .pred p;\n\tsetp.ne.u32 p, %4, 0;\n\t"
                 "tcgen05.mma.cta_group::1.kind::f16 [%0], %1, %2, %3, {%5,%5,%5,%5}, p;\n\t}"
                 :: "r"(d), "l"(ad), "l"(bd), "r"(idesc), "r"(en), "r"(0u) : "memory");
}
// K-major SW128 descriptor: layout=2, version=1, SBO=64, LBO=1 (proven)
__device__ __forceinline__ uint64_t make_desc(uint32_t smem_addr) {
    return ((uint64_t)2 << 61) | ((uint64_t)1 << 46) | ((uint64_t)64 << 32) |
           ((uint64_t)1 << 16) | (((uint64_t)(smem_addr >> 4)) & 0x3FFF);
}
__device__ __forceinline__ void ldtm_x32(uint32_t* r, uint32_t tmem) {
    asm volatile(
        "tcgen05.ld.sync.aligned.32x32b.x32.b32 "
        "{%0,%1,%2,%3,%4,%5,%6,%7,%8,%9,%10,%11,%12,%13,%14,%15,"
        "%16,%17,%18,%19,%20,%21,%22,%23,%24,%25,%26,%27,%28,%29,%30,%31}, [%32];"
        : "=r"(r[0]),"=r"(r[1]),"=r"(r[2]),"=r"(r[3]),"=r"(r[4]),"=r"(r[5]),"=r"(r[6]),"=r"(r[7]),
          "=r"(r[8]),"=r"(r[9]),"=r"(r[10]),"=r"(r[11]),"=r"(r[12]),"=r"(r[13]),"=r"(r[14]),"=r"(r[15]),
          "=r"(r[16]),"=r"(r[17]),"=r"(r[18]),"=r"(r[19]),"=r"(r[20]),"=r"(r[21]),"=r"(r[22]),"=r"(r[23]),
          "=r"(r[24]),"=r"(r[25]),"=r"(r[26]),"=r"(r[27]),"=r"(r[28]),"=r"(r[29]),"=r"(r[30]),"=r"(r[31])
        : "r"(tmem));
}
#endif  // TC_LIVE

// 288 threads. Warp 0 elect = TMA producer; warp 8 elect = MMA issuer;
// warps 0-7 = epilogue. Cluster (4,1,1) along bm: 4 CTAs share one B tile;
// each loads a 64-row slice and multicasts it (MC=1 L2 fetch at csz=4).
__global__ __launch_bounds__(288, 1) __cluster_dims__(CLUSTER, 1, 1)
void gemm_tc_kernel(const __grid_constant__ CUtensorMap tma_a,
                    const __grid_constant__ CUtensorMap tma_b,
                    float* __restrict__ Out) {
#ifdef TC_LIVE
    extern __shared__ char smem_raw[];
    char* smem = (char*)(((uintptr_t)smem_raw + 1023) & ~(uintptr_t)1023);
    const uint32_t sbase = (uint32_t)__cvta_generic_to_shared(smem);
    const uint32_t mbarb = sbase + SMEM_STAGES;
    // full_A[s]: +0,8,16 ; empty_A[s]: +24,32,40 ; full_B[s]: +48,56,64 ;
    // empty_B[s]: +72,80,88 ; fin: +96 ; tmem ptr: +104

    const int tid  = threadIdx.x;
    const int wid  = tid >> 5;
    const int lane = tid & 31;
    const uint32_t rank = cluster_rank();
    const int bm = blockIdx.x * BM;
    const int bn = blockIdx.y * BN;
    const uint16_t ALLMASK = (uint16_t)((1u << CLUSTER) - 1u);  // 0xF

    if (tid == 0) {
#pragma unroll
        for (int s = 0; s < 3; s++) {
            mbar_init(mbarb +      8 * s, 1);        // full_A
            mbar_init(mbarb + 24 + 8 * s, 1);        // empty_A (local commit)
            mbar_init(mbarb + 48 + 8 * s, 1);        // full_B
            mbar_init(mbarb + 72 + 8 * s, CLUSTER);  // empty_B (cluster commits)
        }
        mbar_init(mbarb + 96, 1);                    // fin
    }
    if (wid == 8) {
        asm volatile("tcgen05.alloc.cta_group::1.sync.aligned.shared::cta.b32 [%0], %1;"
                     :: "r"(mbarb + 104), "r"(512) : "memory");
        asm volatile("tcgen05.relinquish_alloc_permit.cta_group::1.sync.aligned;");
    }
    __syncthreads();
    // All cluster CTAs' barriers must exist before any multicast TMA / commit.
    asm volatile("barrier.cluster.arrive.aligned;" ::: "memory");
    asm volatile("barrier.cluster.wait.aligned;" ::: "memory");

    uint32_t tmem;
    asm volatile("ld.shared.b32 %0, [%1];" : "=r"(tmem) : "r"(mbarb + 104));

    const int KT = K_DIM / BK;  // 64

    if (wid == 0 && elect_one()) {
        // ---------------- TMA producer (1 thread) ----------------
        for (int kt = 0; kt < KT; kt++) {
            const int s = kt % 3;
            const uint32_t e_par = ((kt / 3) & 1) ^ 1;   // first 3 uses pass

            // A: private ring — recycles on LOCAL MMA completion only.
            mbar_wait(mbarb + 24 + 8 * s, e_par);
            mbar_expect_tx(mbarb + 8 * s, A_STAGE_BYTES);
            tma_2d(sbase + SMEM_A_BASE + s * A_STAGE_BYTES, &tma_a,
                   kt * BK, bm, mbarb + 8 * s);

            // B: cluster ring — slice multicast to all 4 CTAs.
            mbar_wait(mbarb + 72 + 8 * s, e_par);
            mbar_expect_tx(mbarb + 48 + 8 * s, B_STAGE_BYTES);
            tma_2d_mc(sbase + SMEM_B_BASE + s * B_STAGE_BYTES + rank * B_SLICE_BYTES,
                      &tma_b, kt * BK, bn + (int)rank * B_SLICE_ROWS,
                      mbarb + 48 + 8 * s, ALLMASK);
        }
    } else if (wid == 8 && elect_one()) {
        // ---------------- MMA issuer (1 thread) ----------------
        const uint32_t idesc = (8u << 24) | (16u << 17) | (1u << 4);  // M=128,N=128,f16->f32
        for (int kt = 0; kt < KT; kt++) {
            const int s = kt % 3;
            const uint32_t par = (kt / 3) & 1;
            mbar_wait(mbarb +      8 * s, par);   // full_A
            mbar_wait(mbarb + 48 + 8 * s, par);   // full_B

            uint32_t a_s = sbase + SMEM_A_BASE + s * A_STAGE_BYTES;
            uint32_t b_s = sbase + SMEM_B_BASE + s * B_STAGE_BYTES;
            uint64_t ad0 = make_desc(a_s);
            uint64_t ad1 = make_desc(a_s + 16384);
            uint64_t bd0 = make_desc(b_s);
            uint64_t bd1 = make_desc(b_s + 16384);
#pragma unroll
            for (int ks = 0; ks < 4; ks++) {
                uint32_t en = (kt > 0 || ks > 0) ? 1u : 0u;
                mma_f16_ss(tmem,       ad0 + ks * 2, bd0 + ks * 2, idesc, en);
                mma_f16_ss(tmem + 128, ad0 + ks * 2, bd1 + ks * 2, idesc, en);
                mma_f16_ss(tmem + 256, ad1 + ks * 2, bd0 + ks * 2, idesc, en);
                mma_f16_ss(tmem + 384, ad1 + ks * 2, bd1 + ks * 2, idesc, en);
            }
            tc_commit(mbarb + 24 + 8 * s);            // A: local recycle
            tc_commit_mc(mbarb + 72 + 8 * s, ALLMASK); // B: cluster recycle
        }
        tc_commit(mbarb + 96);
    }

    // All threads: wait for all MMAs to drain
    mbar_wait(mbarb + 96, 0);
    asm volatile("tcgen05.fence::after_thread_sync;" ::: "memory");

    // Epilogue (warps 0-7): warp w -> M-half (w>>2), rows (w&3)*32
    if (wid < 8) {
        const int h   = wid >> 2;
        const int row = bm + h * 128 + (wid & 3) * 32 + lane;
        float* dst = Out + (size_t)row * N_DIM + bn;
        const uint32_t tm = tmem + h * 256;
#pragma unroll
        for (int b = 0; b < 8; b++) {
            uint32_t v[32];
            ldtm_x32(v, tm + b * 32);
            asm volatile("tcgen05.wait::ld.sync.aligned;" ::: "memory");
#pragma unroll
            for (int i = 0; i < 8; i++) {
                float4 f;
                f.x = __uint_as_float(v[4 * i + 0]);
                f.y = __uint_as_float(v[4 * i + 1]);
                f.z = __uint_as_float(v[4 * i + 2]);
                f.w = __uint_as_float(v[4 * i + 3]);
                *reinterpret_cast<float4*>(dst + b * 32 + i * 4) = f;
            }
        }
    }
    __syncthreads();
    if (wid == 8) {
        asm volatile("tcgen05.dealloc.cta_group::1.sync.aligned.b32 %0, %1;"
                     :: "r"(tmem), "r"(512));
    }
    // No CTA may exit while peers could still multicast into its smem.
    asm volatile("barrier.cluster.arrive.aligned;" ::: "memory");
    asm volatile("barrier.cluster.wait.aligned;" ::: "memory");
#endif  // TC_LIVE
}

// ---------------------------------------------------------------------------
typedef CUresult (*EncodeTiledFn)(
    CUtensorMap*, CUtensorMapDataType, cuuint32_t, void*,
    const cuuint64_t*, const cuuint64_t*, const cuuint32_t*, const cuuint32_t*,
    CUtensorMapInterleave, CUtensorMapSwizzle, CUtensorMapL2promotion,
    CUtensorMapFloatOOBfill);

extern "C" void kernel_launch(void* const* d_in, const int* in_sizes, int n_in,
                              void* d_out, int out_size) {
    const float* x  = (const float*)d_in[0];   // [4,2048,4096] fp32 (upcast fp16)
    const int*   qw = (const int*)d_in[1];     // [4096,1376]
    const int*   qz = (const int*)d_in[2];     // [32,1376]
    const float* sc = (const float*)d_in[3];   // [32,11008] fp32 (upcast fp16)
    float* out = (float*)d_out;                // [4,2048,11008] fp32

    cudaFuncSetAttribute(gemm_tc_kernel, cudaFuncAttributeMaxDynamicSharedMemorySize,
                         SMEM_TOTAL);

    // Build TMA descriptors for g_X [M,K] and g_Wt [N,K] (SW128, fp16).
    void* pX = nullptr; void* pW = nullptr;
    cudaGetSymbolAddress(&pX, g_X);
    cudaGetSymbolAddress(&pW, g_Wt);
    EncodeTiledFn enc = nullptr;
    cudaDriverEntryPointQueryResult qr;
    cudaGetDriverEntryPointByVersion("cuTensorMapEncodeTiled", (void**)&enc,
                                     12000, cudaEnableDefault, &qr);
    CUtensorMap ta, tb;
    {
        cuuint64_t dims[2] = {K_DIM, M_DIM};
        cuuint64_t strides[1] = {K_DIM * 2};
        cuuint32_t box[2] = {BK, BM};            // 64 x 256
        cuuint32_t es[2] = {1, 1};
        enc(&ta, CU_TENSOR_MAP_DATA_TYPE_FLOAT16, 2, pX, dims, strides, box, es,
            CU_TENSOR_MAP_INTERLEAVE_NONE, CU_TENSOR_MAP_SWIZZLE_128B,
            CU_TENSOR_MAP_L2_PROMOTION_L2_128B, CU_TENSOR_MAP_FLOAT_OOB_FILL_NONE);
    }
    {
        cuuint64_t dims[2] = {K_DIM, N_DIM};
        cuuint64_t strides[1] = {K_DIM * 2};
        cuuint32_t box[2] = {BK, B_SLICE_ROWS};  // 64 x 64 (cooperative slice)
        cuuint32_t es[2] = {1, 1};
        enc(&tb, CU_TENSOR_MAP_DATA_TYPE_FLOAT16, 2, pW, dims, strides, box, es,
            CU_TENSOR_MAP_INTERLEAVE_NONE, CU_TENSOR_MAP_SWIZZLE_128B,
            CU_TENSOR_MAP_L2_PROMOTION_L2_128B, CU_TENSOR_MAP_FLOAT_OOB_FILL_NONE);
    }

    // Fused prep: x fp32->fp16 + weight dequant-transpose
    prep_kernel<<<N_CONV_BLOCKS + N_DQ_BLOCKS, 256>>>(x, qw, qz, sc);

    dim3 grid(M_DIM / BM, N_DIM / BN);           // (32, 43); clusters of 4 on x
    gemm_tc_kernel<<<grid, 288, SMEM_TOTAL>>>(ta, tb, out);
}

// round 15
// speedup vs baseline: 1.1728x; 1.0013x over previous
#include <cuda_runtime.h>
#include <cuda.h>
#include <cuda_fp16.h>
#include <cstdint>

// Problem constants
#define M_DIM 8192
#define K_DIM 4096
#define N_DIM 11008
#define NP    (N_DIM / 8)

// tcgen05 GEMM: CTA tile 256x256, BK=64, 3 stages, TMA, 2-CTA cluster along M.
// B multicast cooperative slicing. ONE merged full barrier per stage (single
// issuer wait); split empty barriers (A local, B cluster) per R14 finding.
#define BM 256
#define BN 256
#define BK 64
#define CLUSTER 2
#define A_STAGE_BYTES (BM * BK * 2)                     // 32768
#define B_STAGE_BYTES (BN * BK * 2)                     // 32768
#define SMEM_A_BASE   0
#define SMEM_B_BASE   (3 * A_STAGE_BYTES)               // 98304
#define SMEM_STAGES   (6 * A_STAGE_BYTES)               // 196608
#define SMEM_TOTAL    (SMEM_STAGES + 1024 + 128)
#define B_SLICE_ROWS  (BN / CLUSTER)                    // 128
#define B_SLICE_BYTES (B_SLICE_ROWS * BK * 2)           // 16384
#define FULL_TX_BYTES (A_STAGE_BYTES + B_STAGE_BYTES)   // 65536

// Static device scratch
__device__ __half g_Wt[(size_t)N_DIM * K_DIM];  // W transposed [N][K], fp16
__device__ __half g_X [(size_t)M_DIM * K_DIM];  // activations fp16

// ---------------------------------------------------------------------------
// Prep: convert x fp32->fp16 AND dequant AWQ int4 -> g_Wt[n][k], one kernel.
// ---------------------------------------------------------------------------
#define N_CONV_BLOCKS (M_DIM * K_DIM / 4 / 256)         // 32768
#define N_DQ_BLOCKS   ((K_DIM / 64) * (N_DIM / 256))    // 2752

__global__ __launch_bounds__(256)
void prep_kernel(const float* __restrict__ x,
                 const int* __restrict__ qweight,
                 const int* __restrict__ qzeros,
                 const float* __restrict__ scales) {
    const int tid = threadIdx.x;
    if (blockIdx.x < N_CONV_BLOCKS) {
        int i = (blockIdx.x * 256 + tid) * 4;
        float4 v = *reinterpret_cast<const float4*>(x + i);
        __half h[4];
        h[0] = __float2half(v.x); h[1] = __float2half(v.y);
        h[2] = __float2half(v.z); h[3] = __float2half(v.w);
        *reinterpret_cast<uint2*>(&g_X[i]) = *reinterpret_cast<uint2*>(h);
        return;
    }
    const int bid = blockIdx.x - N_CONV_BLOCKS;
    __shared__ __half s[256][64];
    const int k0 = (bid & 63) * 64;
    const int n0 = (bid >> 6) * 256;
    const int g  = k0 >> 7;
    const int c0 = n0 >> 3;

#pragma unroll
    for (int i = 0; i < 8; i++) {
        int lin = tid + 256 * i;
        int cl  = lin & 31;
        int kl  = lin >> 5;
        uint32_t w = (uint32_t)qweight[(size_t)(k0 + kl) * NP + c0 + cl];
        uint32_t z = (uint32_t)qzeros[(size_t)g * NP + c0 + cl];
        const float* sp = scales + (size_t)g * N_DIM + n0 + cl * 8;
#pragma unroll
        for (int j = 0; j < 8; j++) {
            float wi = (float)((w >> (4 * j)) & 15u);
            float zi = (float)((z >> (4 * j)) & 15u);
            __half v = __float2half((wi - zi) * sp[j]);
            int nl = cl * 8 + j;
            int phys16 = (kl >> 3) ^ ((nl >> 3) & 7);
            s[nl][(phys16 << 3) | (kl & 7)] = v;
        }
    }
    __syncthreads();
#pragma unroll
    for (int i = 0; i < 8; i++) {
        int idx = tid + 256 * i;
        int r = idx >> 3, q = idx & 7;
        int phys16 = q ^ ((r >> 3) & 7);
        uint4 v = *reinterpret_cast<uint4*>(&s[r][phys16 << 3]);
        *reinterpret_cast<uint4*>(&g_Wt[(size_t)(n0 + r) * K_DIM + k0 + q * 8]) = v;
    }
}

// ---------------------------------------------------------------------------
// tcgen05 / TMA helpers (device pass targets sm_103a family)
// ---------------------------------------------------------------------------
#if defined(__CUDA_ARCH__) && (defined(__CUDA_ARCH_FEAT_SM103_ALL) || defined(__CUDA_ARCH_FEAT_SM100_ALL) || defined(__CUDA_ARCH_FEAT_SM101_ALL))
#define TC_LIVE 1
#endif

#ifdef TC_LIVE
__device__ __forceinline__ uint32_t elect_one() {
    uint32_t p;
    asm volatile("{\n\t.reg .pred P;\n\telect.sync _|P, 0xFFFFFFFF;\n\t"
                 "selp.b32 %0, 1, 0, P;\n\t}" : "=r"(p));
    return p;
}
__device__ __forceinline__ uint32_t cluster_rank() {
    uint32_t r;
    asm("mov.u32 %0, %%cluster_ctarank;" : "=r"(r));
    return r;
}
__device__ __forceinline__ void mbar_init(uint32_t a, uint32_t cnt) {
    asm volatile("mbarrier.init.shared.b64 [%0], %1;" :: "r"(a), "r"(cnt) : "memory");
}
__device__ __forceinline__ void mbar_wait(uint32_t a, uint32_t parity) {
    asm volatile("{\n\t.reg .pred P;\n\tLW%=:\n\t"
                 "mbarrier.try_wait.parity.acquire.cta.shared::cta.b64 P, [%0], %1;\n\t"
                 "@!P bra LW%=;\n\t}" :: "r"(a), "r"(parity) : "memory");
}
// Relaxed wait: ONLY for producer waits whose post-wait accesses are all
// async-proxy (TMA / mbarrier ops) — per the relaxed-wait rule.
__device__ __forceinline__ void mbar_wait_relaxed(uint32_t a, uint32_t parity) {
    asm volatile("{\n\t.reg .pred P;\n\tLW%=:\n\t"
                 "mbarrier.try_wait.parity.relaxed.cta.shared::cta.b64 P, [%0], %1;\n\t"
                 "@!P bra LW%=;\n\t}" :: "r"(a), "r"(parity) : "memory");
}
__device__ __forceinline__ void mbar_expect_tx(uint32_t a, uint32_t bytes) {
    asm volatile("mbarrier.arrive.expect_tx.shared.b64 _, [%0], %1;"
                 :: "r"(a), "r"(bytes) : "memory");
}
__device__ __forceinline__ void tma_2d(uint32_t dst, const void* map,
                                       int32_t x, int32_t y, uint32_t mbar) {
    asm volatile("cp.async.bulk.tensor.2d.shared::cta.global.tile"
                 ".mbarrier::complete_tx::bytes [%0], [%1, {%2, %3}], [%4];"
                 :: "r"(dst), "l"(map), "r"(x), "r"(y), "r"(mbar) : "memory");
}
__device__ __forceinline__ void tma_2d_mc(uint32_t dst, const void* map,
                                          int32_t x, int32_t y, uint32_t mbar,
                                          uint16_t mask) {
    asm volatile("cp.async.bulk.tensor.2d.shared::cluster.global.tile"
                 ".mbarrier::complete_tx::bytes.multicast::cluster "
                 "[%0], [%1, {%2, %3}], [%4], %5;"
                 :: "r"(dst), "l"(map), "r"(x), "r"(y), "r"(mbar), "h"(mask)
                 : "memory");
}
__device__ __forceinline__ void tc_commit(uint32_t mbar) {
    asm volatile("tcgen05.commit.cta_group::1.mbarrier::arrive::one.shared::cluster.b64 [%0];"
                 :: "r"(mbar) : "memory");
}
__device__ __forceinline__ void tc_commit_mc(uint32_t mbar, uint16_t mask) {
    asm volatile("tcgen05.commit.cta_group::1.mbarrier::arrive::one"
                 ".shared::cluster.multicast::cluster.b64 [%0], %1;"
                 :: "r"(mbar), "h"(mask) : "memory");
}
__device__ __forceinline__ void mma_f16_ss(uint32_t d, uint64_t ad, uint64_t bd,
                                           uint32_t idesc, uint32_t en) {
    asm volatile("{\n\t.reg .pred p;\n\tsetp.ne.u32 p, %4, 0;\n\t"
                 "tcgen05.mma.cta_group::1.kind::f16 [%0], %1, %2, %3, {%5,%5,%5,%5}, p;\n\t}"
                 :: "r"(d), "l"(ad), "l"(bd), "r"(idesc), "r"(en), "r"(0u) : "memory");
}
// K-major SW128 descriptor: layout=2, version=1, SBO=64, LBO=1 (proven)
__device__ __forceinline__ uint64_t make_desc(uint32_t smem_addr) {
    return ((uint64_t)2 << 61) | ((uint64_t)1 << 46) | ((uint64_t)64 << 32) |
           ((uint64_t)1 << 16) | (((uint64_t)(smem_addr >> 4)) & 0x3FFF);
}
__device__ __forceinline__ void ldtm_x32(uint32_t* r, uint32_t tmem) {
    asm volatile(
        "tcgen05.ld.sync.aligned.32x32b.x32.b32 "
        "{%0,%1,%2,%3,%4,%5,%6,%7,%8,%9,%10,%11,%12,%13,%14,%15,"
        "%16,%17,%18,%19,%20,%21,%22,%23,%24,%25,%26,%27,%28,%29,%30,%31}, [%32];"
        : "=r"(r[0]),"=r"(r[1]),"=r"(r[2]),"=r"(r[3]),"=r"(r[4]),"=r"(r[5]),"=r"(r[6]),"=r"(r[7]),
          "=r"(r[8]),"=r"(r[9]),"=r"(r[10]),"=r"(r[11]),"=r"(r[12]),"=r"(r[13]),"=r"(r[14]),"=r"(r[15]),
          "=r"(r[16]),"=r"(r[17]),"=r"(r[18]),"=r"(r[19]),"=r"(r[20]),"=r"(r[21]),"=r"(r[22]),"=r"(r[23]),
          "=r"(r[24]),"=r"(r[25]),"=r"(r[26]),"=r"(r[27]),"=r"(r[28]),"=r"(r[29]),"=r"(r[30]),"=r"(r[31])
        : "r"(tmem));
}
#endif  // TC_LIVE

// 288 threads. Warp 0 elect = TMA producer; warp 8 elect = MMA issuer;
// warps 0-7 = epilogue. Cluster (2,1,1) along bm: pair shares one B tile;
// each CTA loads a 128-row slice and multicasts it to both.
__global__ __launch_bounds__(288, 1) __cluster_dims__(CLUSTER, 1, 1)
void gemm_tc_kernel(const __grid_constant__ CUtensorMap tma_a,
                    const __grid_constant__ CUtensorMap tma_b,
                    float* __restrict__ Out) {
#ifdef TC_LIVE
    extern __shared__ char smem_raw[];
    char* smem = (char*)(((uintptr_t)smem_raw + 1023) & ~(uintptr_t)1023);
    const uint32_t sbase = (uint32_t)__cvta_generic_to_shared(smem);
    const uint32_t mbarb = sbase + SMEM_STAGES;
    // full[s]: +0,8,16 ; empty_A[s]: +24,32,40 ; empty_B[s]: +48,56,64 ;
    // fin: +72 ; tmem ptr: +80

    const int tid  = threadIdx.x;
    const int wid  = tid >> 5;
    const int lane = tid & 31;
    const uint32_t rank = cluster_rank();
    const int bm = blockIdx.x * BM;
    const int bn = blockIdx.y * BN;
    const uint16_t ALLMASK = (uint16_t)((1u << CLUSTER) - 1u);  // 0x3

    if (tid == 0) {
#pragma unroll
        for (int s = 0; s < 3; s++) {
            mbar_init(mbarb +      8 * s, 1);        // full (merged A+B, expect_tx)
            mbar_init(mbarb + 24 + 8 * s, 1);        // empty_A (local commit)
            mbar_init(mbarb + 48 + 8 * s, CLUSTER);  // empty_B (cluster commits)
        }
        mbar_init(mbarb + 72, 1);                    // fin
    }
    if (wid == 8) {
        asm volatile("tcgen05.alloc.cta_group::1.sync.aligned.shared::cta.b32 [%0], %1;"
                     :: "r"(mbarb + 80), "r"(512) : "memory");
        asm volatile("tcgen05.relinquish_alloc_permit.cta_group::1.sync.aligned;");
    }
    __syncthreads();
    // Both CTAs' barriers must exist before any multicast TMA / commit.
    asm volatile("barrier.cluster.arrive.aligned;" ::: "memory");
    asm volatile("barrier.cluster.wait.aligned;" ::: "memory");

    uint32_t tmem;
    asm volatile("ld.shared.b32 %0, [%1];" : "=r"(tmem) : "r"(mbarb + 80));

    const int KT = K_DIM / BK;  // 64

    if (wid == 0 && elect_one()) {
        // ---------------- TMA producer (1 thread) ----------------
        for (int kt = 0; kt < KT; kt++) {
            const int s = kt % 3;
            const uint32_t e_par = ((kt / 3) & 1) ^ 1;   // first 3 uses pass

            mbar_wait_relaxed(mbarb + 24 + 8 * s, e_par);  // empty_A
            mbar_wait_relaxed(mbarb + 48 + 8 * s, e_par);  // empty_B
            const uint32_t full = mbarb + 8 * s;
            mbar_expect_tx(full, FULL_TX_BYTES);           // A 32K + B 2x16K
            tma_2d(sbase + SMEM_A_BASE + s * A_STAGE_BYTES, &tma_a,
                   kt * BK, bm, full);
            tma_2d_mc(sbase + SMEM_B_BASE + s * B_STAGE_BYTES + rank * B_SLICE_BYTES,
                      &tma_b, kt * BK, bn + (int)rank * B_SLICE_ROWS,
                      full, ALLMASK);
        }
    } else if (wid == 8 && elect_one()) {
        // ---------------- MMA issuer (1 thread) ----------------
        const uint32_t idesc = (8u << 24) | (16u << 17) | (1u << 4);  // M=128,N=128,f16->f32
        for (int kt = 0; kt < KT; kt++) {
            const int s = kt % 3;
            mbar_wait(mbarb + 8 * s, (kt / 3) & 1);   // single merged full wait

            uint32_t a_s = sbase + SMEM_A_BASE + s * A_STAGE_BYTES;
            uint32_t b_s = sbase + SMEM_B_BASE + s * B_STAGE_BYTES;
            uint64_t ad0 = make_desc(a_s);
            uint64_t ad1 = make_desc(a_s + 16384);
            uint64_t bd0 = make_desc(b_s);
            uint64_t bd1 = make_desc(b_s + 16384);
#pragma unroll
            for (int ks = 0; ks < 4; ks++) {
                uint32_t en = (kt > 0 || ks > 0) ? 1u : 0u;
                mma_f16_ss(tmem,       ad0 + ks * 2, bd0 + ks * 2, idesc, en);
                mma_f16_ss(tmem + 128, ad0 + ks * 2, bd1 + ks * 2, idesc, en);
                mma_f16_ss(tmem + 256, ad1 + ks * 2, bd0 + ks * 2, idesc, en);
                mma_f16_ss(tmem + 384, ad1 + ks * 2, bd1 + ks * 2, idesc, en);
            }
            tc_commit(mbarb + 24 + 8 * s);             // A: local recycle
            tc_commit_mc(mbarb + 48 + 8 * s, ALLMASK); // B: cluster recycle
        }
        tc_commit(mbarb + 72);
    }

    // All threads: wait for all MMAs to drain
    mbar_wait(mbarb + 72, 0);
    asm volatile("tcgen05.fence::after_thread_sync;" ::: "memory");

    // Epilogue (warps 0-7): warp w -> M-half (w>>2), rows (w&3)*32
    if (wid < 8) {
        const int h   = wid >> 2;
        const int row = bm + h * 128 + (wid & 3) * 32 + lane;
        float* dst = Out + (size_t)row * N_DIM + bn;
        const uint32_t tm = tmem + h * 256;
#pragma unroll
        for (int b = 0; b < 8; b++) {
            uint32_t v[32];
            ldtm_x32(v, tm + b * 32);
            asm volatile("tcgen05.wait::ld.sync.aligned;" ::: "memory");
#pragma unroll
            for (int i = 0; i < 8; i++) {
                float4 f;
                f.x = __uint_as_float(v[4 * i + 0]);
                f.y = __uint_as_float(v[4 * i + 1]);
                f.z = __uint_as_float(v[4 * i + 2]);
                f.w = __uint_as_float(v[4 * i + 3]);
                *reinterpret_cast<float4*>(dst + b * 32 + i * 4) = f;
            }
        }
    }
    __syncthreads();
    if (wid == 8) {
        asm volatile("tcgen05.dealloc.cta_group::1.sync.aligned.b32 %0, %1;"
                     :: "r"(tmem), "r"(512));
    }
    // No CTA may exit while the peer could still multicast into its smem.
    asm volatile("barrier.cluster.arrive.aligned;" ::: "memory");
    asm volatile("barrier.cluster.wait.aligned;" ::: "memory");
#endif  // TC_LIVE
}

// ---------------------------------------------------------------------------
typedef CUresult (*EncodeTiledFn)(
    CUtensorMap*, CUtensorMapDataType, cuuint32_t, void*,
    const cuuint64_t*, const cuuint64_t*, const cuuint32_t*, const cuuint32_t*,
    CUtensorMapInterleave, CUtensorMapSwizzle, CUtensorMapL2promotion,
    CUtensorMapFloatOOBfill);

extern "C" void kernel_launch(void* const* d_in, const int* in_sizes, int n_in,
                              void* d_out, int out_size) {
    const float* x  = (const float*)d_in[0];   // [4,2048,4096] fp32 (upcast fp16)
    const int*   qw = (const int*)d_in[1];     // [4096,1376]
    const int*   qz = (const int*)d_in[2];     // [32,1376]
    const float* sc = (const float*)d_in[3];   // [32,11008] fp32 (upcast fp16)
    float* out = (float*)d_out;                // [4,2048,11008] fp32

    cudaFuncSetAttribute(gemm_tc_kernel, cudaFuncAttributeMaxDynamicSharedMemorySize,
                         SMEM_TOTAL);

    // Build TMA descriptors for g_X [M,K] and g_Wt [N,K] (SW128, fp16).
    void* pX = nullptr; void* pW = nullptr;
    cudaGetSymbolAddress(&pX, g_X);
    cudaGetSymbolAddress(&pW, g_Wt);
    EncodeTiledFn enc = nullptr;
    cudaDriverEntryPointQueryResult qr;
    cudaGetDriverEntryPointByVersion("cuTensorMapEncodeTiled", (void**)&enc,
                                     12000, cudaEnableDefault, &qr);
    CUtensorMap ta, tb;
    {
        cuuint64_t dims[2] = {K_DIM, M_DIM};
        cuuint64_t strides[1] = {K_DIM * 2};
        cuuint32_t box[2] = {BK, BM};            // 64 x 256
        cuuint32_t es[2] = {1, 1};
        enc(&ta, CU_TENSOR_MAP_DATA_TYPE_FLOAT16, 2, pX, dims, strides, box, es,
            CU_TENSOR_MAP_INTERLEAVE_NONE, CU_TENSOR_MAP_SWIZZLE_128B,
            CU_TENSOR_MAP_L2_PROMOTION_L2_128B, CU_TENSOR_MAP_FLOAT_OOB_FILL_NONE);
    }
    {
        cuuint64_t dims[2] = {K_DIM, N_DIM};
        cuuint64_t strides[1] = {K_DIM * 2};
        cuuint32_t box[2] = {BK, B_SLICE_ROWS};  // 64 x 128 (cooperative slice)
        cuuint32_t es[2] = {1, 1};
        enc(&tb, CU_TENSOR_MAP_DATA_TYPE_FLOAT16, 2, pW, dims, strides, box, es,
            CU_TENSOR_MAP_INTERLEAVE_NONE, CU_TENSOR_MAP_SWIZZLE_128B,
            CU_TENSOR_MAP_L2_PROMOTION_L2_128B, CU_TENSOR_MAP_FLOAT_OOB_FILL_NONE);
    }

    // Fused prep: x fp32->fp16 + weight dequant-transpose
    prep_kernel<<<N_CONV_BLOCKS + N_DQ_BLOCKS, 256>>>(x, qw, qz, sc);

    dim3 grid(M_DIM / BM, N_DIM / BN);           // (32, 43); clusters of 2 on x
    gemm_tc_kernel<<<grid, 288, SMEM_TOTAL>>>(ta, tb, out);
}

// round 16
// speedup vs baseline: 1.2580x; 1.0726x over previous
#include <cuda_runtime.h>
#include <cuda.h>
#include <cuda_fp16.h>
#include <cstdint>

// Problem constants
#define M_DIM 8192
#define K_DIM 4096
#define N_DIM 11008
#define NP    (N_DIM / 8)

// cg2 GEMM: pair tile 512(M) x 256(N), BK=64, 4 stages, TMA.
// Per CTA per stage: A = 2 x 128 rows (16KB x2), B = 128 N-rows (16KB).
#define BK 64
#define PAIR_M 512
#define PAIR_N 256
#define A_HALF_BYTES  16384                      // 128 rows x 64 k x 2B
#define B_HALF_BYTES  16384                      // 128 N-rows x 64 k x 2B
#define STAGE_BYTES   (2 * A_HALF_BYTES + B_HALF_BYTES)   // 49152
#define NSTAGES 4
#define SMEM_STAGES   (NSTAGES * STAGE_BYTES)    // 196608
#define SMEM_TOTAL    (SMEM_STAGES + 1024 + 128)
#define FULL_TX_BYTES (2 * STAGE_BYTES)          // both CTAs' loads: 98304

// Static device scratch
__device__ __half g_Wt[(size_t)N_DIM * K_DIM];  // W transposed [N][K], fp16
__device__ __half g_X [(size_t)M_DIM * K_DIM];  // activations fp16

// ---------------------------------------------------------------------------
// Prep: convert x fp32->fp16 AND dequant AWQ int4 -> g_Wt[n][k], one kernel.
// ---------------------------------------------------------------------------
#define N_CONV_BLOCKS (M_DIM * K_DIM / 4 / 256)         // 32768
#define N_DQ_BLOCKS   ((K_DIM / 64) * (N_DIM / 256))    // 2752

__global__ __launch_bounds__(256)
void prep_kernel(const float* __restrict__ x,
                 const int* __restrict__ qweight,
                 const int* __restrict__ qzeros,
                 const float* __restrict__ scales) {
    const int tid = threadIdx.x;
    if (blockIdx.x < N_CONV_BLOCKS) {
        int i = (blockIdx.x * 256 + tid) * 4;
        float4 v = *reinterpret_cast<const float4*>(x + i);
        __half h[4];
        h[0] = __float2half(v.x); h[1] = __float2half(v.y);
        h[2] = __float2half(v.z); h[3] = __float2half(v.w);
        *reinterpret_cast<uint2*>(&g_X[i]) = *reinterpret_cast<uint2*>(h);
        return;
    }
    const int bid = blockIdx.x - N_CONV_BLOCKS;
    __shared__ __half s[256][64];
    const int k0 = (bid & 63) * 64;
    const int n0 = (bid >> 6) * 256;
    const int g  = k0 >> 7;
    const int c0 = n0 >> 3;

#pragma unroll
    for (int i = 0; i < 8; i++) {
        int lin = tid + 256 * i;
        int cl  = lin & 31;
        int kl  = lin >> 5;
        uint32_t w = (uint32_t)qweight[(size_t)(k0 + kl) * NP + c0 + cl];
        uint32_t z = (uint32_t)qzeros[(size_t)g * NP + c0 + cl];
        const float* sp = scales + (size_t)g * N_DIM + n0 + cl * 8;
#pragma unroll
        for (int j = 0; j < 8; j++) {
            float wi = (float)((w >> (4 * j)) & 15u);
            float zi = (float)((z >> (4 * j)) & 15u);
            __half v = __float2half((wi - zi) * sp[j]);
            int nl = cl * 8 + j;
            int phys16 = (kl >> 3) ^ ((nl >> 3) & 7);
            s[nl][(phys16 << 3) | (kl & 7)] = v;
        }
    }
    __syncthreads();
#pragma unroll
    for (int i = 0; i < 8; i++) {
        int idx = tid + 256 * i;
        int r = idx >> 3, q = idx & 7;
        int phys16 = q ^ ((r >> 3) & 7);
        uint4 v = *reinterpret_cast<uint4*>(&s[r][phys16 << 3]);
        *reinterpret_cast<uint4*>(&g_Wt[(size_t)(n0 + r) * K_DIM + k0 + q * 8]) = v;
    }
}

// ---------------------------------------------------------------------------
// tcgen05 / TMA helpers (device pass targets sm_103a family)
// ---------------------------------------------------------------------------
#if defined(__CUDA_ARCH__) && (defined(__CUDA_ARCH_FEAT_SM103_ALL) || defined(__CUDA_ARCH_FEAT_SM100_ALL) || defined(__CUDA_ARCH_FEAT_SM101_ALL))
#define TC_LIVE 1
#endif

#ifdef TC_LIVE
__device__ __forceinline__ uint32_t elect_one() {
    uint32_t p;
    asm volatile("{\n\t.reg .pred P;\n\telect.sync _|P, 0xFFFFFFFF;\n\t"
                 "selp.b32 %0, 1, 0, P;\n\t}" : "=r"(p));
    return p;
}
__device__ __forceinline__ uint32_t cluster_rank() {
    uint32_t r;
    asm("mov.u32 %0, %%cluster_ctarank;" : "=r"(r));
    return r;
}
__device__ __forceinline__ void mbar_init(uint32_t a, uint32_t cnt) {
    asm volatile("mbarrier.init.shared.b64 [%0], %1;" :: "r"(a), "r"(cnt) : "memory");
}
__device__ __forceinline__ void mbar_wait(uint32_t a, uint32_t parity) {
    asm volatile("{\n\t.reg .pred P;\n\tLW%=:\n\t"
                 "mbarrier.try_wait.parity.acquire.cta.shared::cta.b64 P, [%0], %1;\n\t"
                 "@!P bra LW%=;\n\t}" :: "r"(a), "r"(parity) : "memory");
}
__device__ __forceinline__ void mbar_wait_relaxed(uint32_t a, uint32_t parity) {
    asm volatile("{\n\t.reg .pred P;\n\tLW%=:\n\t"
                 "mbarrier.try_wait.parity.relaxed.cta.shared::cta.b64 P, [%0], %1;\n\t"
                 "@!P bra LW%=;\n\t}" :: "r"(a), "r"(parity) : "memory");
}
__device__ __forceinline__ void mbar_expect_tx(uint32_t a, uint32_t bytes) {
    asm volatile("mbarrier.arrive.expect_tx.shared.b64 _, [%0], %1;"
                 :: "r"(a), "r"(bytes) : "memory");
}
// cg2 TMA 2D: both CTAs execute; complete_tx targets the LEADER's barrier
// (clear bit 24 = Sm100MmaPeerBitMask).
__device__ __forceinline__ void tma_2d_cg2(uint32_t dst, const void* map,
                                           int32_t x, int32_t y, uint32_t mbar) {
    asm volatile("{\n\t.reg .b32 lb;\n\tand.b32 lb, %4, 0xFEFFFFFF;\n\t"
                 "cp.async.bulk.tensor.2d.cta_group::2.shared::cluster.global"
                 ".tile.mbarrier::complete_tx::bytes [%0], [%1, {%2, %3}], [lb];\n\t}"
                 :: "r"(dst), "l"(map), "r"(x), "r"(y), "r"(mbar) : "memory");
}
// cg2 commit, multicast to both pair CTAs' barriers at the same offset.
__device__ __forceinline__ void tc_commit_mc_cg2(uint32_t mbar, uint16_t mask) {
    asm volatile("tcgen05.commit.cta_group::2.mbarrier::arrive::one"
                 ".shared::cluster.multicast::cluster.b64 [%0], %1;"
                 :: "r"(mbar), "h"(mask) : "memory");
}
// cg2 f16 SS MMA (verified form from test_2cta_mma_bf16, 8 disable-lane zeros)
__device__ __forceinline__ void mma_f16_ss_cg2(uint32_t d, uint64_t ad, uint64_t bd,
                                               uint32_t idesc, uint32_t en) {
    asm volatile("{\n\t.reg .pred p;\n\tsetp.ne.u32 p, %5, 0;\n\t"
                 "tcgen05.mma.cta_group::2.kind::f16 [%0], %1, %2, %3, "
                 "{%4,%4,%4,%4,%4,%4,%4,%4}, p;\n\t}"
                 :: "r"(d), "l"(ad), "l"(bd), "r"(idesc), "r"(0u), "r"(en)
                 : "memory");
}
// K-major SW128 descriptor: layout=2, version=1, SBO=64, LBO=1 (proven)
__device__ __forceinline__ uint64_t make_desc(uint32_t smem_addr) {
    return ((uint64_t)2 << 61) | ((uint64_t)1 << 46) | ((uint64_t)64 << 32) |
           ((uint64_t)1 << 16) | (((uint64_t)(smem_addr >> 4)) & 0x3FFF);
}
__device__ __forceinline__ void ldtm_x32(uint32_t* r, uint32_t tmem) {
    asm volatile(
        "tcgen05.ld.sync.aligned.32x32b.x32.b32 "
        "{%0,%1,%2,%3,%4,%5,%6,%7,%8,%9,%10,%11,%12,%13,%14,%15,"
        "%16,%17,%18,%19,%20,%21,%22,%23,%24,%25,%26,%27,%28,%29,%30,%31}, [%32];"
        : "=r"(r[0]),"=r"(r[1]),"=r"(r[2]),"=r"(r[3]),"=r"(r[4]),"=r"(r[5]),"=r"(r[6]),"=r"(r[7]),
          "=r"(r[8]),"=r"(r[9]),"=r"(r[10]),"=r"(r[11]),"=r"(r[12]),"=r"(r[13]),"=r"(r[14]),"=r"(r[15]),
          "=r"(r[16]),"=r"(r[17]),"=r"(r[18]),"=r"(r[19]),"=r"(r[20]),"=r"(r[21]),"=r"(r[22]),"=r"(r[23]),
          "=r"(r[24]),"=r"(r[25]),"=r"(r[26]),"=r"(r[27]),"=r"(r[28]),"=r"(r[29]),"=r"(r[30]),"=r"(r[31])
        : "r"(tmem));
}
#endif  // TC_LIVE

// 288 threads. Warp 0 elect = TMA producer; warp 8 elect (leader CTA only) =
// cg2 MMA issuer; warps 0-7 = epilogue. Cluster (2,1,1): rank r holds M-half
// rows r*128 of each cg2 MMA and B N-rows [r*128, r*128+128).
__global__ __launch_bounds__(288, 1) __cluster_dims__(2, 1, 1)
void gemm_tc_kernel(const __grid_constant__ CUtensorMap tma_a,
                    const __grid_constant__ CUtensorMap tma_b,
                    float* __restrict__ Out) {
#ifdef TC_LIVE
    extern __shared__ char smem_raw[];
    char* smem = (char*)(((uintptr_t)smem_raw + 1023) & ~(uintptr_t)1023);
    const uint32_t sbase = (uint32_t)__cvta_generic_to_shared(smem);
    const uint32_t mbarb = sbase + SMEM_STAGES;
    // full[s]: +0..+24 ; empty[s]: +32..+56 ; fin: +64 ; tmem ptr: +72

    const int tid  = threadIdx.x;
    const int wid  = tid >> 5;
    const int lane = tid & 31;
    const uint32_t rank = cluster_rank();
    const int pm = blockIdx.x >> 1;              // pair index along M
    const int bn = blockIdx.y * PAIR_N;
    const int pair_m0 = pm * PAIR_M;

    if (tid == 0) {
#pragma unroll
        for (int s = 0; s < NSTAGES; s++) {
            mbar_init(mbarb +      8 * s, 1);    // full: leader expect_tx
            mbar_init(mbarb + 32 + 8 * s, 1);    // empty: 1 multicast commit
        }
        mbar_init(mbarb + 64, 1);                // fin
    }
    if (wid == 8) {
        asm volatile("tcgen05.alloc.cta_group::2.sync.aligned.shared::cta.b32 [%0], %1;"
                     :: "r"(mbarb + 72), "r"(512) : "memory");
        asm volatile("tcgen05.relinquish_alloc_permit.cta_group::2.sync.aligned;");
    }
    __syncthreads();
    // Pair barriers must exist before any cg2 TMA / multicast commit.
    asm volatile("barrier.cluster.arrive.aligned;" ::: "memory");
    asm volatile("barrier.cluster.wait.aligned;" ::: "memory");

    uint32_t tmem;
    asm volatile("ld.shared.b32 %0, [%1];" : "=r"(tmem) : "r"(mbarb + 72));

    const int KT = K_DIM / BK;  // 64

    if (wid == 0 && elect_one()) {
        // ------------- TMA producer (1 thread per CTA, both CTAs) -------------
        for (int kt = 0; kt < KT; kt++) {
            const int s = kt & (NSTAGES - 1);
            const uint32_t e_par = ((kt / NSTAGES) & 1) ^ 1;  // first 4 uses pass
            mbar_wait_relaxed(mbarb + 32 + 8 * s, e_par);

            const uint32_t full = mbarb + 8 * s;
            if (rank == 0)
                mbar_expect_tx(full, FULL_TX_BYTES);          // pair total 96KB
            uint32_t st = sbase + s * STAGE_BYTES;
            // A: this CTA's 128 rows of each M-half (cg2 M=256 split)
            tma_2d_cg2(st,                 &tma_a, kt * BK,
                       pair_m0 +       (int)rank * 128, full);
            tma_2d_cg2(st + A_HALF_BYTES,  &tma_a, kt * BK,
                       pair_m0 + 256 + (int)rank * 128, full);
            // B: this CTA's 128 N-rows (cg2 N=256 split, same local offset)
            tma_2d_cg2(st + 2 * A_HALF_BYTES, &tma_b, kt * BK,
                       bn + (int)rank * 128, full);
        }
    } else if (rank == 0 && wid == 8 && elect_one()) {
        // ------------- cg2 MMA issuer (leader CTA, 1 thread) -------------
        // M=256 (pair), N=256, f16 in, f32 acc
        const uint32_t idesc = (16u << 24) | (32u << 17) | (1u << 4);
        for (int kt = 0; kt < KT; kt++) {
            const int s = kt & (NSTAGES - 1);
            mbar_wait(mbarb + 8 * s, (kt / NSTAGES) & 1);

            uint32_t st = sbase + s * STAGE_BYTES;
            uint64_t ad0 = make_desc(st);
            uint64_t ad1 = make_desc(st + A_HALF_BYTES);
            uint64_t bd  = make_desc(st + 2 * A_HALF_BYTES);
#pragma unroll
            for (int ks = 0; ks < 4; ks++) {
                uint32_t en = (kt > 0 || ks > 0) ? 1u : 0u;
                mma_f16_ss_cg2(tmem,       ad0 + ks * 2, bd + ks * 2, idesc, en);
                mma_f16_ss_cg2(tmem + 256, ad1 + ks * 2, bd + ks * 2, idesc, en);
            }
            tc_commit_mc_cg2(mbarb + 32 + 8 * s, (uint16_t)0x3);
        }
        tc_commit_mc_cg2(mbarb + 64, (uint16_t)0x3);
    }

    // All threads (both CTAs): wait for all MMAs to drain
    mbar_wait(mbarb + 64, 0);
    asm volatile("tcgen05.fence::after_thread_sync;" ::: "memory");

    // Epilogue: warp w -> M-half h=w>>2 (TMEM cols h*256), subpartition w&3.
    // Global row = pair_m0 + h*256 + rank*128 + (w&3)*32 + lane.
    if (wid < 8) {
        const int h   = wid >> 2;
        const int row = pair_m0 + h * 256 + (int)rank * 128 + (wid & 3) * 32 + lane;
        float* dst = Out + (size_t)row * N_DIM + bn;
        const uint32_t tm = tmem + h * 256;
#pragma unroll
        for (int b = 0; b < 8; b++) {
            uint32_t v[32];
            ldtm_x32(v, tm + b * 32);
            asm volatile("tcgen05.wait::ld.sync.aligned;" ::: "memory");
#pragma unroll
            for (int i = 0; i < 8; i++) {
                float4 f;
                f.x = __uint_as_float(v[4 * i + 0]);
                f.y = __uint_as_float(v[4 * i + 1]);
                f.z = __uint_as_float(v[4 * i + 2]);
                f.w = __uint_as_float(v[4 * i + 3]);
                *reinterpret_cast<float4*>(dst + b * 32 + i * 4) = f;
            }
        }
    }
    __syncthreads();
    if (wid == 8) {
        asm volatile("tcgen05.dealloc.cta_group::2.sync.aligned.b32 %0, %1;"
                     :: "r"(tmem), "r"(512));
    }
    // No CTA may exit while the peer could still signal/read this CTA.
    asm volatile("barrier.cluster.arrive.aligned;" ::: "memory");
    asm volatile("barrier.cluster.wait.aligned;" ::: "memory");
#endif  // TC_LIVE
}

// ---------------------------------------------------------------------------
typedef CUresult (*EncodeTiledFn)(
    CUtensorMap*, CUtensorMapDataType, cuuint32_t, void*,
    const cuuint64_t*, const cuuint64_t*, const cuuint32_t*, const cuuint32_t*,
    CUtensorMapInterleave, CUtensorMapSwizzle, CUtensorMapL2promotion,
    CUtensorMapFloatOOBfill);

extern "C" void kernel_launch(void* const* d_in, const int* in_sizes, int n_in,
                              void* d_out, int out_size) {
    const float* x  = (const float*)d_in[0];   // [4,2048,4096] fp32 (upcast fp16)
    const int*   qw = (const int*)d_in[1];     // [4096,1376]
    const int*   qz = (const int*)d_in[2];     // [32,1376]
    const float* sc = (const float*)d_in[3];   // [32,11008] fp32 (upcast fp16)
    float* out = (float*)d_out;                // [4,2048,11008] fp32

    cudaFuncSetAttribute(gemm_tc_kernel, cudaFuncAttributeMaxDynamicSharedMemorySize,
                         SMEM_TOTAL);

    // TMA descriptors: g_X [M,K] and g_Wt [N,K], SW128, fp16, box 64x128.
    void* pX = nullptr; void* pW = nullptr;
    cudaGetSymbolAddress(&pX, g_X);
    cudaGetSymbolAddress(&pW, g_Wt);
    EncodeTiledFn enc = nullptr;
    cudaDriverEntryPointQueryResult qr;
    cudaGetDriverEntryPointByVersion("cuTensorMapEncodeTiled", (void**)&enc,
                                     12000, cudaEnableDefault, &qr);
    CUtensorMap ta, tb;
    {
        cuuint64_t dims[2] = {K_DIM, M_DIM};
        cuuint64_t strides[1] = {K_DIM * 2};
        cuuint32_t box[2] = {BK, 128};
        cuuint32_t es[2] = {1, 1};
        enc(&ta, CU_TENSOR_MAP_DATA_TYPE_FLOAT16, 2, pX, dims, strides, box, es,
            CU_TENSOR_MAP_INTERLEAVE_NONE, CU_TENSOR_MAP_SWIZZLE_128B,
            CU_TENSOR_MAP_L2_PROMOTION_L2_128B, CU_TENSOR_MAP_FLOAT_OOB_FILL_NONE);
    }
    {
        cuuint64_t dims[2] = {K_DIM, N_DIM};
        cuuint64_t strides[1] = {K_DIM * 2};
        cuuint32_t box[2] = {BK, 128};
        cuuint32_t es[2] = {1, 1};
        enc(&tb, CU_TENSOR_MAP_DATA_TYPE_FLOAT16, 2, pW, dims, strides, box, es,
            CU_TENSOR_MAP_INTERLEAVE_NONE, CU_TENSOR_MAP_SWIZZLE_128B,
            CU_TENSOR_MAP_L2_PROMOTION_L2_128B, CU_TENSOR_MAP_FLOAT_OOB_FILL_NONE);
    }

    // Fused prep: x fp32->fp16 + weight dequant-transpose
    prep_kernel<<<N_CONV_BLOCKS + N_DQ_BLOCKS, 256>>>(x, qw, qz, sc);

    // Grid: 32 CTAs along M (16 cg2 pairs x cluster 2), 43 along N.
    dim3 grid(M_DIM / PAIR_M * 2, N_DIM / PAIR_N);   // (32, 43)
    gemm_tc_kernel<<<grid, 288, SMEM_TOTAL>>>(ta, tb, out);
}